// round 10
// baseline (speedup 1.0000x reference)
#include <cuda_runtime.h>

#define LDIM 26
#define KCOMP 64
#define BN 262144
#define NITER 8
#define WFLOOR 1e-5f
#define VFLOOR 1e-6f
#define LOG_PI_C 47.784803726642978f   // 26 * log(2*pi)
#define SHIFT 40.0f                    // fixed logit shift (replaces per-row max)

#define NBLK_E 592            // estep blocks (128 thr = 4 warps), 4 per SM
#define TILE_E 128
#define NBLK_M 592            // mstat blocks (256 thr), 4 per SM
#define TILE_M 32
#define NTILE_M (BN / TILE_M) // 8192
#define NSLOT NBLK_M          // 592 partial slots (one per block)
#define RHALF (NSLOT / 2)     // 296 slots per reduce-half
#define OUT_N (KCOMP + KCOMP*LDIM + KCOMP*LDIM*LDIM + 1)   // 44993

// ---------------- device state (no allocation allowed) ----------------
__device__ float g_w[KCOMP];
__device__ float g_mu[KCOMP * LDIM];
__device__ float g_sig[KCOMP * LDIM];
__device__ float g_Phn[KCOMP * LDIM];    // -0.5 / sigma
__device__ float g_MP[KCOMP * LDIM];     // mu / sigma
__device__ float g_C[KCOMP];             // log w - 0.5*(LOG_PI + logdet + quad) + SHIFT
__device__ float g_post[(size_t)BN * KCOMP];          // 64 MiB posterior
__device__ float g_part[(size_t)NSLOT * KCOMP * 54];  // 8.2MB partials
__device__ float g_stat2[2][KCOMP * 54];
__device__ float g_llp[NBLK_E];
__device__ float g_ll;

// ---------------- init: normalize w0, copy mu0 / sigma0 ----------------
__global__ void k_init(const float* __restrict__ w0,
                       const float* __restrict__ mu0,
                       const float* __restrict__ s0) {
    __shared__ float s_sum;
    if (threadIdx.x == 0) {
        float s = 0.f;
        for (int k = 0; k < KCOMP; k++) s += w0[k];
        s_sum = s;
    }
    __syncthreads();
    for (int i = threadIdx.x; i < KCOMP * LDIM; i += blockDim.x) {
        g_mu[i]  = mu0[i];
        g_sig[i] = s0[i];
    }
    if (threadIdx.x < KCOMP) g_w[threadIdx.x] = w0[threadIdx.x] / s_sum;
}

// ---------------- prep (initial only) ----------------
__global__ void k_prep() {
    int k = blockIdx.x;
    int lane = threadIdx.x;
    float ld = 0.f, qd = 0.f;
    if (lane < LDIM) {
        float sg = g_sig[k * LDIM + lane];
        float mu = g_mu[k * LDIM + lane];
        float pr = 1.0f / sg;
        g_Phn[k * LDIM + lane] = -0.5f * pr;
        g_MP[k * LDIM + lane] = mu * pr;
        ld = logf(sg);
        qd = mu * mu * pr;
    }
    #pragma unroll
    for (int o = 16; o; o >>= 1) {
        ld += __shfl_xor_sync(0xffffffffu, ld, o);
        qd += __shfl_xor_sync(0xffffffffu, qd, o);
    }
    if (lane == 0)
        g_C[k] = logf(g_w[k]) - 0.5f * (LOG_PI_C + ld + qd) + SHIFT;
}

// ---------------- E-step: 2-warp cooperative softmax, 1 comp per lane -------
// warp pair (2p, 2p+1): warp half 0 -> comps 0-31, half 1 -> comps 32-63.
// Pair processes 4 rows per batch; row-sums combined via smem + __syncthreads.
__global__ void __launch_bounds__(128, 4) k_estep(const float* __restrict__ x) {
    __shared__ __align__(16) float xt[TILE_E * 28];
    __shared__ __align__(16) float sp[2][4][4];   // [buf][warp][row]
    __shared__ float sll[4];
    int tid = threadIdx.x;
    int lane = tid & 31;
    int warp = tid >> 5;
    int pair = warp >> 1;
    int half = warp & 1;
    int k = (half << 5) + lane;

    // zero pads once (staging never writes c>=26)
    for (int r = tid; r < TILE_E; r += 128) {
        xt[r * 28 + 26] = 0.f;
        xt[r * 28 + 27] = 0.f;
    }

    float MP[28], Ph[28];
    #pragma unroll
    for (int l = 0; l < LDIM; l++) {
        MP[l] = g_MP[k * LDIM + l];
        Ph[l] = g_Phn[k * LDIM + l];
    }
    #pragma unroll
    for (int l = LDIM; l < 28; l++) { MP[l] = 0.f; Ph[l] = 0.f; }
    float C = g_C[k];
    float llacc = 0.f;

    for (int t = blockIdx.x; t < BN / TILE_E; t += NBLK_E) {
        int rowbase = t * TILE_E;
        __syncthreads();
        // stage 128 rows x 26 floats = 832 float4
        const float4* src = (const float4*)(x + (size_t)rowbase * LDIM);
        for (int i = tid; i < TILE_E * LDIM / 4; i += 128) {
            float4 v = src[i];
            int e = i * 4;
            float vv[4] = {v.x, v.y, v.z, v.w};
            #pragma unroll
            for (int j = 0; j < 4; j++) {
                int idx = e + j;
                xt[(idx / LDIM) * 28 + (idx % LDIM)] = vv[j];
            }
        }
        __syncthreads();
        #pragma unroll 1
        for (int b = 0; b < 16; b++) {
            int r0 = (pair << 6) + (b << 2);
            const float4* R0 = (const float4*)(xt + r0 * 28);
            const float4* R1 = (const float4*)(xt + (r0 + 1) * 28);
            const float4* R2 = (const float4*)(xt + (r0 + 2) * 28);
            const float4* R3 = (const float4*)(xt + (r0 + 3) * 28);
            float n0 = C, n1 = C, n2 = C, n3 = C;
            #pragma unroll
            for (int i = 0; i < 7; i++) {
                float4 a = R0[i], bb = R1[i], c = R2[i], d = R3[i];
                #pragma unroll
                for (int j = 0; j < 4; j++) {
                    int l = 4 * i + j;
                    float av = j == 0 ? a.x : j == 1 ? a.y : j == 2 ? a.z : a.w;
                    float bv = j == 0 ? bb.x : j == 1 ? bb.y : j == 2 ? bb.z : bb.w;
                    float cv = j == 0 ? c.x : j == 1 ? c.y : j == 2 ? c.z : c.w;
                    float dv = j == 0 ? d.x : j == 1 ? d.y : j == 2 ? d.z : d.w;
                    float t0 = fmaf(av, Ph[l], MP[l]); n0 = fmaf(av, t0, n0);
                    float t1 = fmaf(bv, Ph[l], MP[l]); n1 = fmaf(bv, t1, n1);
                    float t2 = fmaf(cv, Ph[l], MP[l]); n2 = fmaf(cv, t2, n2);
                    float t3 = fmaf(dv, Ph[l], MP[l]); n3 = fmaf(dv, t3, n3);
                }
            }
            float e0 = __expf(n0), e1 = __expf(n1);
            float e2 = __expf(n2), e3 = __expf(n3);
            float s0 = e0, s1 = e1, s2 = e2, s3 = e3;
            #pragma unroll
            for (int o = 16; o; o >>= 1) {
                s0 += __shfl_xor_sync(0xffffffffu, s0, o);
                s1 += __shfl_xor_sync(0xffffffffu, s1, o);
                s2 += __shfl_xor_sync(0xffffffffu, s2, o);
                s3 += __shfl_xor_sync(0xffffffffu, s3, o);
            }
            if (lane == 0)
                *(float4*)sp[b & 1][warp] = make_float4(s0, s1, s2, s3);
            __syncthreads();
            float4 o4 = *(const float4*)sp[b & 1][warp ^ 1];
            float t0 = s0 + o4.x, t1 = s1 + o4.y;
            float t2 = s2 + o4.z, t3 = s3 + o4.w;
            float p0 = e0 * __frcp_rn(t0);
            float p1 = e1 * __frcp_rn(t1);
            float p2 = e2 * __frcp_rn(t2);
            float p3 = e3 * __frcp_rn(t3);
            float* P = g_post + (size_t)(rowbase + r0) * KCOMP + k;
            P[0]         = p0;
            P[KCOMP]     = p1;
            P[2 * KCOMP] = p2;
            P[3 * KCOMP] = p3;
            if (lane == 0 && half == 0)
                llacc += (__logf(t0) - SHIFT) + (__logf(t1) - SHIFT)
                       + (__logf(t2) - SHIFT) + (__logf(t3) - SHIFT);
        }
    }
    if (lane == 0) sll[warp] = llacc;
    __syncthreads();
    if (tid == 0)
        g_llp[blockIdx.x] = sll[0] + sll[1] + sll[2] + sll[3];
}

// ---------------- M-step stats: warp = (khalf, h, rowgrp); p staged in smem -
// thread: k = lane + 32*khalf; h=0 accumulates z+px over x, h=1 pxx over x^2
__global__ void __launch_bounds__(256, 4) k_mstat(const float* __restrict__ x) {
    __shared__ __align__(16) float xs[TILE_M][28];
    __shared__ __align__(16) float x2s[TILE_M][28];
    __shared__ __align__(16) float ps[TILE_M][KCOMP];
    __shared__ float comb[128 * 29];
    int tid = threadIdx.x;
    int lane = tid & 31;
    int warp = tid >> 5;
    int khalf = warp & 1;
    int h = (warp >> 1) & 1;
    int rgrp = warp >> 2;            // 0 or 1 -> 16 rows each
    int k = lane + (khalf << 5);

    if (tid < TILE_M) {
        xs[tid][26] = 0.f;  xs[tid][27] = 0.f;
        x2s[tid][26] = 0.f; x2s[tid][27] = 0.f;
    }

    float z = 0.f;
    float acc[28];
    #pragma unroll
    for (int j = 0; j < 28; j++) acc[j] = 0.f;

    for (int t = blockIdx.x; t < NTILE_M; t += NBLK_M) {
        int rowbase = t * TILE_M;
        __syncthreads();
        // stage 32 rows x 26 floats = 208 float4
        if (tid < 208) {
            float4 v = ((const float4*)(x + (size_t)rowbase * LDIM))[tid];
            int e = tid * 4;
            float vv[4] = {v.x, v.y, v.z, v.w};
            #pragma unroll
            for (int j = 0; j < 4; j++) {
                int idx = e + j;
                int r = idx / LDIM, c = idx % LDIM;
                xs[r][c] = vv[j];
                x2s[r][c] = vv[j] * vv[j];
            }
        }
        // stage 32 rows x 64 posteriors = 512 float4
        {
            const float4* psrc = (const float4*)(g_post + (size_t)rowbase * KCOMP);
            float4 p0 = psrc[tid];
            float4 p1 = psrc[tid + 256];
            ((float4*)ps)[tid] = p0;
            ((float4*)ps)[tid + 256] = p1;
        }
        __syncthreads();
        #pragma unroll
        for (int rr = 0; rr < 16; rr++) {
            int r = rgrp * 16 + rr;
            float p = ps[r][k];
            z += p;
            const float4* V = (const float4*)(h ? x2s[r] : xs[r]);
            #pragma unroll
            for (int i = 0; i < 7; i++) {
                float4 v = V[i];
                acc[4*i]   = fmaf(p, v.x, acc[4*i]);
                acc[4*i+1] = fmaf(p, v.y, acc[4*i+1]);
                acc[4*i+2] = fmaf(p, v.z, acc[4*i+2]);
                acc[4*i+3] = fmaf(p, v.w, acc[4*i+3]);
            }
        }
    }
    // combine rgrp=1 into rgrp=0 via smem, then one partial slot per block
    __syncthreads();
    if (rgrp == 1) {
        float* c = comb + ((warp & 3) * 32 + lane) * 29;
        #pragma unroll
        for (int j = 0; j < 26; j++) c[j] = acc[j];
        c[26] = z;
    }
    __syncthreads();
    if (rgrp == 0) {
        const float* c = comb + (warp * 32 + lane) * 29;
        #pragma unroll
        for (int j = 0; j < 26; j++) acc[j] += c[j];
        z += c[26];
        float* dst = g_part + ((size_t)blockIdx.x * KCOMP + k) * 54;
        if (h == 0) {
            dst[0] = z;
            #pragma unroll
            for (int j = 0; j < 26; j++) dst[1 + j] = acc[j];
        } else {
            #pragma unroll
            for (int j = 0; j < 26; j++) dst[27 + j] = acc[j];
        }
    }
}

// ---------------- reduce partials: one block per (k, slot-half) ----------------
__global__ void __launch_bounds__(256) k_reduce() {
    __shared__ float red[4][54];
    int bk = blockIdx.x >> 1;
    int half = blockIdx.x & 1;
    int tid = threadIdx.x;
    int j = tid & 63;
    int s = tid >> 6;
    if (j < 54) {
        float acc = 0.f;
        int base = half * RHALF;
        for (int slot = s; slot < RHALF; slot += 4)
            acc += g_part[((size_t)(base + slot) * KCOMP + bk) * 54 + j];
        red[s][j] = acc;
    }
    __syncthreads();
    if (tid < 54)
        g_stat2[half][bk * 54 + tid] = red[0][tid] + red[1][tid] + red[2][tid] + red[3][tid];
}

// ---------------- M-step finalize + fused prep ----------------
__global__ void __launch_bounds__(256) k_mstep() {
    __shared__ float s_w[KCOMP];
    __shared__ float s_ab[2];
    __shared__ float s_llp[64];
    int tid = threadIdx.x;

    if (tid < KCOMP) {
        float zk = g_stat2[0][tid * 54] + g_stat2[1][tid * 54];
        s_w[tid] = fmaxf(zk * (1.0f / BN), WFLOOR);
        float l = 0.f;
        for (int i = tid; i < NBLK_E; i += 64) l += g_llp[i];
        s_llp[tid] = l;
    }
    __syncthreads();
    if (tid == 0) {
        float sum = 0.f, ll = 0.f;
        for (int k = 0; k < KCOMP; k++) { sum += s_w[k]; ll += s_llp[k]; }
        float sf = WFLOOR * KCOMP;
        float a = (1.0f - sf) / (sum - sf);
        s_ab[0] = a;
        s_ab[1] = WFLOOR * (1.0f - a);
        g_ll = ll;
    }
    __syncthreads();
    if (tid < KCOMP) g_w[tid] = s_ab[0] * s_w[tid] + s_ab[1];

    for (int idx = tid; idx < KCOMP * LDIM; idx += 256) {
        int k = idx / LDIM, l = idx % LDIM;
        float z = g_stat2[0][k * 54] + g_stat2[1][k * 54];
        float zi = 1.0f / z;
        float px = g_stat2[0][k * 54 + 1 + l] + g_stat2[1][k * 54 + 1 + l];
        float pxx = g_stat2[0][k * 54 + 27 + l] + g_stat2[1][k * 54 + 27 + l];
        float mu = px * zi;
        float sg = fmaxf(pxx * zi - mu * mu, VFLOOR);
        g_mu[idx] = mu;
        g_sig[idx] = sg;
    }
    __syncthreads();

    int warp = tid >> 5, lane = tid & 31;
    for (int k = warp; k < KCOMP; k += 8) {
        float ld = 0.f, qd = 0.f;
        if (lane < LDIM) {
            float sg = g_sig[k * LDIM + lane];
            float mu = g_mu[k * LDIM + lane];
            float pr = 1.0f / sg;
            g_Phn[k * LDIM + lane] = -0.5f * pr;
            g_MP[k * LDIM + lane] = mu * pr;
            ld = logf(sg);
            qd = mu * mu * pr;
        }
        #pragma unroll
        for (int o = 16; o; o >>= 1) {
            ld += __shfl_xor_sync(0xffffffffu, ld, o);
            qd += __shfl_xor_sync(0xffffffffu, qd, o);
        }
        if (lane == 0)
            g_C[k] = logf(g_w[k]) - 0.5f * (LOG_PI_C + ld + qd) + SHIFT;
    }
}

// ---------------- output: w | mu | diag-expanded sigma | ll ----------------
__global__ void k_write(float* __restrict__ out) {
    int i = blockIdx.x * 256 + threadIdx.x;
    if (i >= OUT_N) return;
    float v;
    if (i < KCOMP) {
        v = g_w[i];
    } else if (i < KCOMP + KCOMP * LDIM) {
        v = g_mu[i - KCOMP];
    } else if (i < KCOMP + KCOMP * LDIM + KCOMP * LDIM * LDIM) {
        int j = i - (KCOMP + KCOMP * LDIM);
        int k = j / (LDIM * LDIM);
        int rc = j % (LDIM * LDIM);
        int r = rc / LDIM, c = rc % LDIM;
        v = (r == c) ? g_sig[k * LDIM + r] : 0.f;
    } else {
        v = g_ll;
    }
    out[i] = v;
}

extern "C" void kernel_launch(void* const* d_in, const int* in_sizes, int n_in,
                              void* d_out, int out_size) {
    const float* x   = (const float*)d_in[0];
    const float* w0  = (const float*)d_in[1];
    const float* mu0 = (const float*)d_in[2];
    const float* s0  = (const float*)d_in[3];
    float* out = (float*)d_out;

    k_init<<<1, 256>>>(w0, mu0, s0);
    k_prep<<<KCOMP, 32>>>();
    for (int it = 0; it < NITER; it++) {
        k_estep<<<NBLK_E, 128>>>(x);
        k_mstat<<<NBLK_M, 256>>>(x);
        k_reduce<<<KCOMP * 2, 256>>>();
        k_mstep<<<1, 256>>>();
    }
    k_write<<<(OUT_N + 255) / 256, 256>>>(out);
}

// round 11
// speedup vs baseline: 1.1818x; 1.1818x over previous
#include <cuda_runtime.h>

#define LDIM 26
#define KCOMP 64
#define BN 262144
#define NITER 8
#define WFLOOR 1e-5f
#define VFLOOR 1e-6f
#define LOG_PI_C 47.784803726642978f   // 26 * log(2*pi)
#define SHIFT 40.0f                    // fixed logit shift (replaces per-row max)

#define NBLK_E 444            // estep blocks (128 thr = 4 warps)
#define TILE_E 128
#define NBLK_M 444            // mstat blocks (256 thr), 3 per SM
#define TILE_M 32
#define NTILE_M (BN / TILE_M) // 8192
#define NSLOT NBLK_M          // 444 partial slots (one per block)
#define RHALF (NSLOT / 2)     // 222 slots per reduce-half
#define OUT_N (KCOMP + KCOMP*LDIM + KCOMP*LDIM*LDIM + 1)   // 44993

// ---------------- device state (no allocation allowed) ----------------
__device__ float g_w[KCOMP];
__device__ float g_mu[KCOMP * LDIM];
__device__ float g_sig[KCOMP * LDIM];
__device__ float g_Phn[KCOMP * LDIM];    // -0.5 / sigma
__device__ float g_MP[KCOMP * LDIM];     // mu / sigma
__device__ float g_C[KCOMP];             // log w - 0.5*(LOG_PI + logdet + quad) + SHIFT
__device__ float g_post[(size_t)BN * KCOMP];          // 64 MiB posterior
__device__ float g_part[(size_t)NSLOT * KCOMP * 54];  // 6.1MB partials
__device__ float g_stat2[2][KCOMP * 54];
__device__ float g_llp[NBLK_E];
__device__ float g_ll;

// ---------------- init: normalize w0, copy mu0 / sigma0 ----------------
__global__ void k_init(const float* __restrict__ w0,
                       const float* __restrict__ mu0,
                       const float* __restrict__ s0) {
    __shared__ float s_sum;
    if (threadIdx.x == 0) {
        float s = 0.f;
        for (int k = 0; k < KCOMP; k++) s += w0[k];
        s_sum = s;
    }
    __syncthreads();
    for (int i = threadIdx.x; i < KCOMP * LDIM; i += blockDim.x) {
        g_mu[i]  = mu0[i];
        g_sig[i] = s0[i];
    }
    if (threadIdx.x < KCOMP) g_w[threadIdx.x] = w0[threadIdx.x] / s_sum;
}

// ---------------- prep (initial only) ----------------
__global__ void k_prep() {
    int k = blockIdx.x;
    int lane = threadIdx.x;
    float ld = 0.f, qd = 0.f;
    if (lane < LDIM) {
        float sg = g_sig[k * LDIM + lane];
        float mu = g_mu[k * LDIM + lane];
        float pr = 1.0f / sg;
        g_Phn[k * LDIM + lane] = -0.5f * pr;
        g_MP[k * LDIM + lane] = mu * pr;
        ld = logf(sg);
        qd = mu * mu * pr;
    }
    #pragma unroll
    for (int o = 16; o; o >>= 1) {
        ld += __shfl_xor_sync(0xffffffffu, ld, o);
        qd += __shfl_xor_sync(0xffffffffu, qd, o);
    }
    if (lane == 0)
        g_C[k] = logf(g_w[k]) - 0.5f * (LOG_PI_C + ld + qd) + SHIFT;
}

// ---------------- E-step (round-8 proven): x-only smem tile, warp-per-2-rows,
// fixed-shift softmax; lane owns comps k=lane and k+32.
__global__ void __launch_bounds__(128) k_estep(const float* __restrict__ x) {
    __shared__ __align__(16) float xt[TILE_E * 28];
    __shared__ float sll[4];
    int tid = threadIdx.x;
    int lane = tid & 31;
    int warp = tid >> 5;

    for (int r = tid; r < TILE_E; r += 128) {
        xt[r * 28 + 26] = 0.f;
        xt[r * 28 + 27] = 0.f;
    }

    float MP0[28], Ph0[28], MP1[28], Ph1[28];
    #pragma unroll
    for (int l = 0; l < LDIM; l++) {
        MP0[l] = g_MP[lane * LDIM + l];
        Ph0[l] = g_Phn[lane * LDIM + l];
        MP1[l] = g_MP[(lane + 32) * LDIM + l];
        Ph1[l] = g_Phn[(lane + 32) * LDIM + l];
    }
    #pragma unroll
    for (int l = LDIM; l < 28; l++) {
        MP0[l] = 0.f; Ph0[l] = 0.f; MP1[l] = 0.f; Ph1[l] = 0.f;
    }
    float C0 = g_C[lane], C1 = g_C[lane + 32];
    float llacc = 0.f;

    for (int t = blockIdx.x; t < BN / TILE_E; t += NBLK_E) {
        int rowbase = t * TILE_E;
        __syncthreads();
        const float4* src = (const float4*)(x + (size_t)rowbase * LDIM);
        for (int i = tid; i < TILE_E * LDIM / 4; i += 128) {
            float4 v = src[i];
            int e = i * 4;
            float vv[4] = {v.x, v.y, v.z, v.w};
            #pragma unroll
            for (int j = 0; j < 4; j++) {
                int idx = e + j;
                xt[(idx / LDIM) * 28 + (idx % LDIM)] = vv[j];
            }
        }
        __syncthreads();
        #pragma unroll 1
        for (int it = 0; it < 16; it++) {
            int r0 = warp * 32 + it * 2;
            const float4* A = (const float4*)(xt + r0 * 28);
            const float4* B = (const float4*)(xt + (r0 + 1) * 28);
            float n00 = C0, n01 = C1, n10 = C0, n11 = C1;
            #pragma unroll
            for (int i = 0; i < 7; i++) {
                float4 a = A[i];
                float4 b = B[i];
                #pragma unroll
                for (int j = 0; j < 4; j++) {
                    int l = 4 * i + j;
                    float ax = j == 0 ? a.x : j == 1 ? a.y : j == 2 ? a.z : a.w;
                    float bx = j == 0 ? b.x : j == 1 ? b.y : j == 2 ? b.z : b.w;
                    float t0 = fmaf(ax, Ph0[l], MP0[l]);
                    n00 = fmaf(ax, t0, n00);
                    float t1 = fmaf(ax, Ph1[l], MP1[l]);
                    n01 = fmaf(ax, t1, n01);
                    float u0 = fmaf(bx, Ph0[l], MP0[l]);
                    n10 = fmaf(bx, u0, n10);
                    float u1 = fmaf(bx, Ph1[l], MP1[l]);
                    n11 = fmaf(bx, u1, n11);
                }
            }
            float e00 = __expf(n00), e01 = __expf(n01);
            float e10 = __expf(n10), e11 = __expf(n11);
            float s0 = e00 + e01, s1 = e10 + e11;
            #pragma unroll
            for (int o = 16; o; o >>= 1) {
                s0 += __shfl_xor_sync(0xffffffffu, s0, o);
                s1 += __shfl_xor_sync(0xffffffffu, s1, o);
            }
            float rs0 = __frcp_rn(s0), rs1 = __frcp_rn(s1);
            float* P0 = g_post + (size_t)(rowbase + r0) * KCOMP;
            P0[lane]              = e00 * rs0;
            P0[lane + 32]         = e01 * rs0;
            P0[KCOMP + lane]      = e10 * rs1;
            P0[KCOMP + lane + 32] = e11 * rs1;
            if (lane == 0)
                llacc += (__logf(s0) - SHIFT) + (__logf(s1) - SHIFT);
        }
    }
    if (lane == 0) sll[warp] = llacc;
    __syncthreads();
    if (tid == 0)
        g_llp[blockIdx.x] = sll[0] + sll[1] + sll[2] + sll[3];
}

// ---------------- M-step stats: khalf merged; warp = (h, rgrp) --------------
// thread owns comps k0=lane, k1=lane+32.  h=0: z + px over x;  h=1: pxx over x^2.
// Per row per warp: 2 LDS.32 (p pair) + 7 broadcast LDS.128 (x or x^2).
__global__ void __launch_bounds__(256, 3) k_mstat(const float* __restrict__ x) {
    __shared__ __align__(16) float xs[TILE_M][28];
    __shared__ __align__(16) float x2s[TILE_M][28];
    __shared__ __align__(16) float ps[TILE_M][KCOMP];
    __shared__ float comb[2][2][KCOMP][27];   // [slot][h][k][z|26 vals]
    int tid = threadIdx.x;
    int lane = tid & 31;
    int warp = tid >> 5;
    int h = warp & 1;
    int rgrp = warp >> 1;            // 0..3, 8 rows each
    int k0 = lane, k1 = lane + 32;

    if (tid < TILE_M) {
        xs[tid][26] = 0.f;  xs[tid][27] = 0.f;
        x2s[tid][26] = 0.f; x2s[tid][27] = 0.f;
    }

    float z0 = 0.f, z1 = 0.f;
    float a0[26], a1[26];
    #pragma unroll
    for (int j = 0; j < 26; j++) { a0[j] = 0.f; a1[j] = 0.f; }

    for (int t = blockIdx.x; t < NTILE_M; t += NBLK_M) {
        int rowbase = t * TILE_M;
        __syncthreads();
        // stage 32 rows x 26 floats = 208 float4
        if (tid < 208) {
            float4 v = ((const float4*)(x + (size_t)rowbase * LDIM))[tid];
            int e = tid * 4;
            float vv[4] = {v.x, v.y, v.z, v.w};
            #pragma unroll
            for (int j = 0; j < 4; j++) {
                int idx = e + j;
                int r = idx / LDIM, c = idx % LDIM;
                xs[r][c] = vv[j];
                x2s[r][c] = vv[j] * vv[j];
            }
        }
        // stage 32 rows x 64 posteriors = 512 float4
        {
            const float4* psrc = (const float4*)(g_post + (size_t)rowbase * KCOMP);
            ((float4*)ps)[tid] = psrc[tid];
            ((float4*)ps)[tid + 256] = psrc[tid + 256];
        }
        __syncthreads();
        #pragma unroll
        for (int rr = 0; rr < 8; rr++) {
            int r = rgrp * 8 + rr;
            float p0 = ps[r][k0];
            float p1 = ps[r][k1];
            const float* row = h ? x2s[r] : xs[r];
            const float4* V = (const float4*)row;
            if (h == 0) { z0 += p0; z1 += p1; }
            #pragma unroll
            for (int i = 0; i < 6; i++) {
                float4 v = V[i];
                a0[4*i]   = fmaf(p0, v.x, a0[4*i]);
                a1[4*i]   = fmaf(p1, v.x, a1[4*i]);
                a0[4*i+1] = fmaf(p0, v.y, a0[4*i+1]);
                a1[4*i+1] = fmaf(p1, v.y, a1[4*i+1]);
                a0[4*i+2] = fmaf(p0, v.z, a0[4*i+2]);
                a1[4*i+2] = fmaf(p1, v.z, a1[4*i+2]);
                a0[4*i+3] = fmaf(p0, v.w, a0[4*i+3]);
                a1[4*i+3] = fmaf(p1, v.w, a1[4*i+3]);
            }
            float4 v6 = V[6];
            a0[24] = fmaf(p0, v6.x, a0[24]);
            a1[24] = fmaf(p1, v6.x, a1[24]);
            a0[25] = fmaf(p0, v6.y, a0[25]);
            a1[25] = fmaf(p1, v6.y, a1[25]);
        }
    }

    // ---- combine rgrps 0..3 -> rgrp 0, then one partial slot per block ----
    __syncthreads();
    if (rgrp >= 2) {
        int slot = rgrp - 2;
        comb[slot][h][k0][0] = z0;
        comb[slot][h][k1][0] = z1;
        #pragma unroll
        for (int j = 0; j < 26; j++) {
            comb[slot][h][k0][1 + j] = a0[j];
            comb[slot][h][k1][1 + j] = a1[j];
        }
    }
    __syncthreads();
    if (rgrp < 2) {
        z0 += comb[rgrp][h][k0][0];
        z1 += comb[rgrp][h][k1][0];
        #pragma unroll
        for (int j = 0; j < 26; j++) {
            a0[j] += comb[rgrp][h][k0][1 + j];
            a1[j] += comb[rgrp][h][k1][1 + j];
        }
    }
    __syncthreads();
    if (rgrp == 1) {
        comb[0][h][k0][0] = z0;
        comb[0][h][k1][0] = z1;
        #pragma unroll
        for (int j = 0; j < 26; j++) {
            comb[0][h][k0][1 + j] = a0[j];
            comb[0][h][k1][1 + j] = a1[j];
        }
    }
    __syncthreads();
    if (rgrp == 0) {
        z0 += comb[0][h][k0][0];
        z1 += comb[0][h][k1][0];
        #pragma unroll
        for (int j = 0; j < 26; j++) {
            a0[j] += comb[0][h][k0][1 + j];
            a1[j] += comb[0][h][k1][1 + j];
        }
        float* d0 = g_part + ((size_t)blockIdx.x * KCOMP + k0) * 54;
        float* d1 = g_part + ((size_t)blockIdx.x * KCOMP + k1) * 54;
        if (h == 0) {
            d0[0] = z0;
            d1[0] = z1;
            #pragma unroll
            for (int j = 0; j < 26; j++) { d0[1 + j] = a0[j]; d1[1 + j] = a1[j]; }
        } else {
            #pragma unroll
            for (int j = 0; j < 26; j++) { d0[27 + j] = a0[j]; d1[27 + j] = a1[j]; }
        }
    }
}

// ---------------- reduce partials: one block per (k, slot-half) ----------------
__global__ void __launch_bounds__(256) k_reduce() {
    __shared__ float red[4][54];
    int bk = blockIdx.x >> 1;
    int half = blockIdx.x & 1;
    int tid = threadIdx.x;
    int j = tid & 63;
    int s = tid >> 6;
    if (j < 54) {
        float acc = 0.f;
        int base = half * RHALF;
        for (int slot = s; slot < RHALF; slot += 4)
            acc += g_part[((size_t)(base + slot) * KCOMP + bk) * 54 + j];
        red[s][j] = acc;
    }
    __syncthreads();
    if (tid < 54)
        g_stat2[half][bk * 54 + tid] = red[0][tid] + red[1][tid] + red[2][tid] + red[3][tid];
}

// ---------------- M-step finalize + fused prep ----------------
__global__ void __launch_bounds__(256) k_mstep() {
    __shared__ float s_w[KCOMP];
    __shared__ float s_ab[2];
    __shared__ float s_llp[64];
    int tid = threadIdx.x;

    if (tid < KCOMP) {
        float zk = g_stat2[0][tid * 54] + g_stat2[1][tid * 54];
        s_w[tid] = fmaxf(zk * (1.0f / BN), WFLOOR);
        float l = 0.f;
        for (int i = tid; i < NBLK_E; i += 64) l += g_llp[i];
        s_llp[tid] = l;
    }
    __syncthreads();
    if (tid == 0) {
        float sum = 0.f, ll = 0.f;
        for (int k = 0; k < KCOMP; k++) { sum += s_w[k]; ll += s_llp[k]; }
        float sf = WFLOOR * KCOMP;
        float a = (1.0f - sf) / (sum - sf);
        s_ab[0] = a;
        s_ab[1] = WFLOOR * (1.0f - a);
        g_ll = ll;
    }
    __syncthreads();
    if (tid < KCOMP) g_w[tid] = s_ab[0] * s_w[tid] + s_ab[1];

    for (int idx = tid; idx < KCOMP * LDIM; idx += 256) {
        int k = idx / LDIM, l = idx % LDIM;
        float z = g_stat2[0][k * 54] + g_stat2[1][k * 54];
        float zi = 1.0f / z;
        float px = g_stat2[0][k * 54 + 1 + l] + g_stat2[1][k * 54 + 1 + l];
        float pxx = g_stat2[0][k * 54 + 27 + l] + g_stat2[1][k * 54 + 27 + l];
        float mu = px * zi;
        float sg = fmaxf(pxx * zi - mu * mu, VFLOOR);
        g_mu[idx] = mu;
        g_sig[idx] = sg;
    }
    __syncthreads();

    int warp = tid >> 5, lane = tid & 31;
    for (int k = warp; k < KCOMP; k += 8) {
        float ld = 0.f, qd = 0.f;
        if (lane < LDIM) {
            float sg = g_sig[k * LDIM + lane];
            float mu = g_mu[k * LDIM + lane];
            float pr = 1.0f / sg;
            g_Phn[k * LDIM + lane] = -0.5f * pr;
            g_MP[k * LDIM + lane] = mu * pr;
            ld = logf(sg);
            qd = mu * mu * pr;
        }
        #pragma unroll
        for (int o = 16; o; o >>= 1) {
            ld += __shfl_xor_sync(0xffffffffu, ld, o);
            qd += __shfl_xor_sync(0xffffffffu, qd, o);
        }
        if (lane == 0)
            g_C[k] = logf(g_w[k]) - 0.5f * (LOG_PI_C + ld + qd) + SHIFT;
    }
}

// ---------------- output: w | mu | diag-expanded sigma | ll ----------------
__global__ void k_write(float* __restrict__ out) {
    int i = blockIdx.x * 256 + threadIdx.x;
    if (i >= OUT_N) return;
    float v;
    if (i < KCOMP) {
        v = g_w[i];
    } else if (i < KCOMP + KCOMP * LDIM) {
        v = g_mu[i - KCOMP];
    } else if (i < KCOMP + KCOMP * LDIM + KCOMP * LDIM * LDIM) {
        int j = i - (KCOMP + KCOMP * LDIM);
        int k = j / (LDIM * LDIM);
        int rc = j % (LDIM * LDIM);
        int r = rc / LDIM, c = rc % LDIM;
        v = (r == c) ? g_sig[k * LDIM + r] : 0.f;
    } else {
        v = g_ll;
    }
    out[i] = v;
}

extern "C" void kernel_launch(void* const* d_in, const int* in_sizes, int n_in,
                              void* d_out, int out_size) {
    const float* x   = (const float*)d_in[0];
    const float* w0  = (const float*)d_in[1];
    const float* mu0 = (const float*)d_in[2];
    const float* s0  = (const float*)d_in[3];
    float* out = (float*)d_out;

    k_init<<<1, 256>>>(w0, mu0, s0);
    k_prep<<<KCOMP, 32>>>();
    for (int it = 0; it < NITER; it++) {
        k_estep<<<NBLK_E, 128>>>(x);
        k_mstat<<<NBLK_M, 256>>>(x);
        k_reduce<<<KCOMP * 2, 256>>>();
        k_mstep<<<1, 256>>>();
    }
    k_write<<<(OUT_N + 255) / 256, 256>>>(out);
}

// round 12
// speedup vs baseline: 1.2751x; 1.0789x over previous
#include <cuda_runtime.h>

#define LDIM 26
#define KCOMP 64
#define BN 262144
#define NITER 8
#define WFLOOR 1e-5f
#define VFLOOR 1e-6f
#define LOG_PI_C 47.784803726642978f   // 26 * log(2*pi)
#define SHIFT 40.0f                    // fixed logit shift (replaces per-row max)

#define NBLK_E 740            // estep blocks (128 thr = 4 warps), ~5 per SM
#define TILE_E 64
#define NTILE_E (BN / TILE_E) // 4096
#define NBLK_M 444            // mstat blocks (256 thr), 3 per SM
#define TILE_M 32
#define NTILE_M (BN / TILE_M) // 8192
#define NSLOT NBLK_M          // 444 partial slots (one per block)
#define RHALF (NSLOT / 2)     // 222 slots per reduce-half
#define OUT_N (KCOMP + KCOMP*LDIM + KCOMP*LDIM*LDIM + 1)   // 44993

// ---------------- device state (no allocation allowed) ----------------
__device__ float g_w[KCOMP];
__device__ float g_mu[KCOMP * LDIM];
__device__ float g_sig[KCOMP * LDIM];
__device__ float g_Phn[KCOMP * LDIM];    // -0.5 / sigma
__device__ float g_MP[KCOMP * LDIM];     // mu / sigma
__device__ float g_C[KCOMP];             // log w - 0.5*(LOG_PI + logdet + quad) + SHIFT
__device__ float g_post[(size_t)BN * KCOMP];          // 64 MiB posterior
__device__ float g_part[(size_t)NSLOT * KCOMP * 54];  // 6.1MB partials
__device__ float g_stat2[2][KCOMP * 54];
__device__ float g_llp[NBLK_E];
__device__ float g_ll;

// ---------------- init: normalize w0, copy mu0 / sigma0 ----------------
__global__ void k_init(const float* __restrict__ w0,
                       const float* __restrict__ mu0,
                       const float* __restrict__ s0) {
    __shared__ float s_sum;
    if (threadIdx.x == 0) {
        float s = 0.f;
        for (int k = 0; k < KCOMP; k++) s += w0[k];
        s_sum = s;
    }
    __syncthreads();
    for (int i = threadIdx.x; i < KCOMP * LDIM; i += blockDim.x) {
        g_mu[i]  = mu0[i];
        g_sig[i] = s0[i];
    }
    if (threadIdx.x < KCOMP) g_w[threadIdx.x] = w0[threadIdx.x] / s_sum;
}

// ---------------- prep (initial only) ----------------
__global__ void k_prep() {
    int k = blockIdx.x;
    int lane = threadIdx.x;
    float ld = 0.f, qd = 0.f;
    if (lane < LDIM) {
        float sg = g_sig[k * LDIM + lane];
        float mu = g_mu[k * LDIM + lane];
        float pr = 1.0f / sg;
        g_Phn[k * LDIM + lane] = -0.5f * pr;
        g_MP[k * LDIM + lane] = mu * pr;
        ld = logf(sg);
        qd = mu * mu * pr;
    }
    #pragma unroll
    for (int o = 16; o; o >>= 1) {
        ld += __shfl_xor_sync(0xffffffffu, ld, o);
        qd += __shfl_xor_sync(0xffffffffu, qd, o);
    }
    if (lane == 0)
        g_C[k] = logf(g_w[k]) - 0.5f * (LOG_PI_C + ld + qd) + SHIFT;
}

// ---------------- E-step: phase-separated, 1 comp per lane ------------------
// warp = (rowhalf, khalf).  Phase1: logits+exp -> swizzled smem e-tile.
// Phase2a: 2 threads/row sum 64 e's -> rs, ll.  Phase2b: scale + coalesced store.
// e storage: quad q of row r lives at quad index r*16 + (q ^ (r&7)).
__global__ void __launch_bounds__(128, 5) k_estep(const float* __restrict__ x) {
    __shared__ __align__(16) float xt[TILE_E * 28];
    __shared__ __align__(16) float es[TILE_E * KCOMP];
    __shared__ float rs_s[TILE_E];
    __shared__ float lls[TILE_E];
    int tid = threadIdx.x;
    int lane = tid & 31;
    int warp = tid >> 5;
    int rowhalf = warp >> 1;
    int khalf = warp & 1;
    int k = (khalf << 5) + lane;

    float MP[LDIM], Ph[LDIM];
    #pragma unroll
    for (int l = 0; l < LDIM; l++) {
        MP[l] = g_MP[k * LDIM + l];
        Ph[l] = g_Phn[k * LDIM + l];
    }
    float C = g_C[k];
    float llacc = 0.f;
    int r2a = tid >> 1;      // phase2a row (0..63)
    int half2a = tid & 1;

    for (int t = blockIdx.x; t < NTILE_E; t += NBLK_E) {
        int rowbase = t * TILE_E;
        __syncthreads();
        // stage 64 rows x 26 floats = 416 float4
        const float4* src = (const float4*)(x + (size_t)rowbase * LDIM);
        for (int i = tid; i < TILE_E * LDIM / 4; i += 128) {
            float4 v = src[i];
            int e = i * 4;
            float vv[4] = {v.x, v.y, v.z, v.w};
            #pragma unroll
            for (int j = 0; j < 4; j++) {
                int idx = e + j;
                xt[(idx / LDIM) * 28 + (idx % LDIM)] = vv[j];
            }
        }
        __syncthreads();
        // ---- phase 1: logits + exp for 32 rows x 32 comps per warp ----
        int rbase = rowhalf << 5;
        int kq = k >> 2, k3 = k & 3;
        #pragma unroll 1
        for (int it = 0; it < 16; it++) {
            int ra = rbase + it * 2;
            int rb = ra + 1;
            const float4* A = (const float4*)(xt + ra * 28);
            const float4* B = (const float4*)(xt + rb * 28);
            float na = C, nb = C;
            #pragma unroll
            for (int i = 0; i < 6; i++) {
                float4 a = A[i];
                float4 b = B[i];
                #pragma unroll
                for (int j = 0; j < 4; j++) {
                    int l = 4 * i + j;
                    float av = j == 0 ? a.x : j == 1 ? a.y : j == 2 ? a.z : a.w;
                    float bv = j == 0 ? b.x : j == 1 ? b.y : j == 2 ? b.z : b.w;
                    float t0 = fmaf(av, Ph[l], MP[l]); na = fmaf(av, t0, na);
                    float t1 = fmaf(bv, Ph[l], MP[l]); nb = fmaf(bv, t1, nb);
                }
            }
            float2 a2 = *(const float2*)(xt + ra * 28 + 24);
            float2 b2 = *(const float2*)(xt + rb * 28 + 24);
            float u0 = fmaf(a2.x, Ph[24], MP[24]); na = fmaf(a2.x, u0, na);
            float u1 = fmaf(a2.y, Ph[25], MP[25]); na = fmaf(a2.y, u1, na);
            float u2 = fmaf(b2.x, Ph[24], MP[24]); nb = fmaf(b2.x, u2, nb);
            float u3 = fmaf(b2.y, Ph[25], MP[25]); nb = fmaf(b2.y, u3, nb);
            float ea = __expf(na), eb = __expf(nb);
            es[(ra << 6) + ((kq ^ (ra & 7)) << 2) + k3] = ea;
            es[(rb << 6) + ((kq ^ (rb & 7)) << 2) + k3] = eb;
        }
        __syncthreads();
        // ---- phase 2a: row sums -> rs, ll ----
        {
            const float4* e4 = (const float4*)es;
            int sbase = r2a << 4;
            int ss = r2a & 7;
            float s = 0.f;
            #pragma unroll
            for (int j = 0; j < 8; j++) {
                float4 v = e4[sbase + (half2a << 3) + (j ^ ss)];
                s += (v.x + v.y) + (v.z + v.w);
            }
            s += __shfl_xor_sync(0xffffffffu, s, 1);
            if (half2a == 0) {
                rs_s[r2a] = __frcp_rn(s);
                llacc += __logf(s) - SHIFT;
            }
        }
        __syncthreads();
        // ---- phase 2b: scale + coalesced store ----
        {
            const float4* e4 = (const float4*)es;
            float4* pout = (float4*)(g_post + (size_t)rowbase * KCOMP);
            #pragma unroll
            for (int i = 0; i < 8; i++) {
                int f = (i << 7) + tid;          // 0..1023 flat float4 index
                int r = f >> 4, q = f & 15;
                float4 v = e4[(r << 4) + (q ^ (r & 7))];
                float rsv = rs_s[r];
                v.x *= rsv; v.y *= rsv; v.z *= rsv; v.w *= rsv;
                pout[f] = v;
            }
        }
    }
    __syncthreads();
    if ((tid & 1) == 0) lls[tid >> 1] = llacc;
    __syncthreads();
    if (tid == 0) {
        float s = 0.f;
        for (int i = 0; i < TILE_E; i++) s += lls[i];
        g_llp[blockIdx.x] = s;
    }
}

// ---------------- M-step stats: khalf merged; warp = (h, rgrp) --------------
__global__ void __launch_bounds__(256, 3) k_mstat(const float* __restrict__ x) {
    __shared__ __align__(16) float xs[TILE_M][28];
    __shared__ __align__(16) float x2s[TILE_M][28];
    __shared__ __align__(16) float ps[TILE_M][KCOMP];
    __shared__ float comb[2][2][KCOMP][27];   // [slot][h][k][z|26 vals]
    int tid = threadIdx.x;
    int lane = tid & 31;
    int warp = tid >> 5;
    int h = warp & 1;
    int rgrp = warp >> 1;            // 0..3, 8 rows each
    int k0 = lane, k1 = lane + 32;

    if (tid < TILE_M) {
        xs[tid][26] = 0.f;  xs[tid][27] = 0.f;
        x2s[tid][26] = 0.f; x2s[tid][27] = 0.f;
    }

    float z0 = 0.f, z1 = 0.f;
    float a0[26], a1[26];
    #pragma unroll
    for (int j = 0; j < 26; j++) { a0[j] = 0.f; a1[j] = 0.f; }

    for (int t = blockIdx.x; t < NTILE_M; t += NBLK_M) {
        int rowbase = t * TILE_M;
        __syncthreads();
        if (tid < 208) {
            float4 v = ((const float4*)(x + (size_t)rowbase * LDIM))[tid];
            int e = tid * 4;
            float vv[4] = {v.x, v.y, v.z, v.w};
            #pragma unroll
            for (int j = 0; j < 4; j++) {
                int idx = e + j;
                int r = idx / LDIM, c = idx % LDIM;
                xs[r][c] = vv[j];
                x2s[r][c] = vv[j] * vv[j];
            }
        }
        {
            const float4* psrc = (const float4*)(g_post + (size_t)rowbase * KCOMP);
            ((float4*)ps)[tid] = psrc[tid];
            ((float4*)ps)[tid + 256] = psrc[tid + 256];
        }
        __syncthreads();
        #pragma unroll
        for (int rr = 0; rr < 8; rr++) {
            int r = rgrp * 8 + rr;
            float p0 = ps[r][k0];
            float p1 = ps[r][k1];
            const float* row = h ? x2s[r] : xs[r];
            const float4* V = (const float4*)row;
            if (h == 0) { z0 += p0; z1 += p1; }
            #pragma unroll
            for (int i = 0; i < 6; i++) {
                float4 v = V[i];
                a0[4*i]   = fmaf(p0, v.x, a0[4*i]);
                a1[4*i]   = fmaf(p1, v.x, a1[4*i]);
                a0[4*i+1] = fmaf(p0, v.y, a0[4*i+1]);
                a1[4*i+1] = fmaf(p1, v.y, a1[4*i+1]);
                a0[4*i+2] = fmaf(p0, v.z, a0[4*i+2]);
                a1[4*i+2] = fmaf(p1, v.z, a1[4*i+2]);
                a0[4*i+3] = fmaf(p0, v.w, a0[4*i+3]);
                a1[4*i+3] = fmaf(p1, v.w, a1[4*i+3]);
            }
            float4 v6 = V[6];
            a0[24] = fmaf(p0, v6.x, a0[24]);
            a1[24] = fmaf(p1, v6.x, a1[24]);
            a0[25] = fmaf(p0, v6.y, a0[25]);
            a1[25] = fmaf(p1, v6.y, a1[25]);
        }
    }

    __syncthreads();
    if (rgrp >= 2) {
        int slot = rgrp - 2;
        comb[slot][h][k0][0] = z0;
        comb[slot][h][k1][0] = z1;
        #pragma unroll
        for (int j = 0; j < 26; j++) {
            comb[slot][h][k0][1 + j] = a0[j];
            comb[slot][h][k1][1 + j] = a1[j];
        }
    }
    __syncthreads();
    if (rgrp < 2) {
        z0 += comb[rgrp][h][k0][0];
        z1 += comb[rgrp][h][k1][0];
        #pragma unroll
        for (int j = 0; j < 26; j++) {
            a0[j] += comb[rgrp][h][k0][1 + j];
            a1[j] += comb[rgrp][h][k1][1 + j];
        }
    }
    __syncthreads();
    if (rgrp == 1) {
        comb[0][h][k0][0] = z0;
        comb[0][h][k1][0] = z1;
        #pragma unroll
        for (int j = 0; j < 26; j++) {
            comb[0][h][k0][1 + j] = a0[j];
            comb[0][h][k1][1 + j] = a1[j];
        }
    }
    __syncthreads();
    if (rgrp == 0) {
        z0 += comb[0][h][k0][0];
        z1 += comb[0][h][k1][0];
        #pragma unroll
        for (int j = 0; j < 26; j++) {
            a0[j] += comb[0][h][k0][1 + j];
            a1[j] += comb[0][h][k1][1 + j];
        }
        float* d0 = g_part + ((size_t)blockIdx.x * KCOMP + k0) * 54;
        float* d1 = g_part + ((size_t)blockIdx.x * KCOMP + k1) * 54;
        if (h == 0) {
            d0[0] = z0;
            d1[0] = z1;
            #pragma unroll
            for (int j = 0; j < 26; j++) { d0[1 + j] = a0[j]; d1[1 + j] = a1[j]; }
        } else {
            #pragma unroll
            for (int j = 0; j < 26; j++) { d0[27 + j] = a0[j]; d1[27 + j] = a1[j]; }
        }
    }
}

// ---------------- reduce partials: one block per (k, slot-half) ----------------
__global__ void __launch_bounds__(256) k_reduce() {
    __shared__ float red[4][54];
    int bk = blockIdx.x >> 1;
    int half = blockIdx.x & 1;
    int tid = threadIdx.x;
    int j = tid & 63;
    int s = tid >> 6;
    if (j < 54) {
        float acc = 0.f;
        int base = half * RHALF;
        for (int slot = s; slot < RHALF; slot += 4)
            acc += g_part[((size_t)(base + slot) * KCOMP + bk) * 54 + j];
        red[s][j] = acc;
    }
    __syncthreads();
    if (tid < 54)
        g_stat2[half][bk * 54 + tid] = red[0][tid] + red[1][tid] + red[2][tid] + red[3][tid];
}

// ---------------- M-step finalize + fused prep ----------------
__global__ void __launch_bounds__(256) k_mstep() {
    __shared__ float s_w[KCOMP];
    __shared__ float s_ab[2];
    __shared__ float s_llp[64];
    int tid = threadIdx.x;

    if (tid < KCOMP) {
        float zk = g_stat2[0][tid * 54] + g_stat2[1][tid * 54];
        s_w[tid] = fmaxf(zk * (1.0f / BN), WFLOOR);
        float l = 0.f;
        for (int i = tid; i < NBLK_E; i += 64) l += g_llp[i];
        s_llp[tid] = l;
    }
    __syncthreads();
    if (tid == 0) {
        float sum = 0.f, ll = 0.f;
        for (int k = 0; k < KCOMP; k++) { sum += s_w[k]; ll += s_llp[k]; }
        float sf = WFLOOR * KCOMP;
        float a = (1.0f - sf) / (sum - sf);
        s_ab[0] = a;
        s_ab[1] = WFLOOR * (1.0f - a);
        g_ll = ll;
    }
    __syncthreads();
    if (tid < KCOMP) g_w[tid] = s_ab[0] * s_w[tid] + s_ab[1];

    for (int idx = tid; idx < KCOMP * LDIM; idx += 256) {
        int k = idx / LDIM, l = idx % LDIM;
        float z = g_stat2[0][k * 54] + g_stat2[1][k * 54];
        float zi = 1.0f / z;
        float px = g_stat2[0][k * 54 + 1 + l] + g_stat2[1][k * 54 + 1 + l];
        float pxx = g_stat2[0][k * 54 + 27 + l] + g_stat2[1][k * 54 + 27 + l];
        float mu = px * zi;
        float sg = fmaxf(pxx * zi - mu * mu, VFLOOR);
        g_mu[idx] = mu;
        g_sig[idx] = sg;
    }
    __syncthreads();

    int warp = tid >> 5, lane = tid & 31;
    for (int k = warp; k < KCOMP; k += 8) {
        float ld = 0.f, qd = 0.f;
        if (lane < LDIM) {
            float sg = g_sig[k * LDIM + lane];
            float mu = g_mu[k * LDIM + lane];
            float pr = 1.0f / sg;
            g_Phn[k * LDIM + lane] = -0.5f * pr;
            g_MP[k * LDIM + lane] = mu * pr;
            ld = logf(sg);
            qd = mu * mu * pr;
        }
        #pragma unroll
        for (int o = 16; o; o >>= 1) {
            ld += __shfl_xor_sync(0xffffffffu, ld, o);
            qd += __shfl_xor_sync(0xffffffffu, qd, o);
        }
        if (lane == 0)
            g_C[k] = logf(g_w[k]) - 0.5f * (LOG_PI_C + ld + qd) + SHIFT;
    }
}

// ---------------- output: w | mu | diag-expanded sigma | ll ----------------
__global__ void k_write(float* __restrict__ out) {
    int i = blockIdx.x * 256 + threadIdx.x;
    if (i >= OUT_N) return;
    float v;
    if (i < KCOMP) {
        v = g_w[i];
    } else if (i < KCOMP + KCOMP * LDIM) {
        v = g_mu[i - KCOMP];
    } else if (i < KCOMP + KCOMP * LDIM + KCOMP * LDIM * LDIM) {
        int j = i - (KCOMP + KCOMP * LDIM);
        int k = j / (LDIM * LDIM);
        int rc = j % (LDIM * LDIM);
        int r = rc / LDIM, c = rc % LDIM;
        v = (r == c) ? g_sig[k * LDIM + r] : 0.f;
    } else {
        v = g_ll;
    }
    out[i] = v;
}

extern "C" void kernel_launch(void* const* d_in, const int* in_sizes, int n_in,
                              void* d_out, int out_size) {
    const float* x   = (const float*)d_in[0];
    const float* w0  = (const float*)d_in[1];
    const float* mu0 = (const float*)d_in[2];
    const float* s0  = (const float*)d_in[3];
    float* out = (float*)d_out;

    k_init<<<1, 256>>>(w0, mu0, s0);
    k_prep<<<KCOMP, 32>>>();
    for (int it = 0; it < NITER; it++) {
        k_estep<<<NBLK_E, 128>>>(x);
        k_mstat<<<NBLK_M, 256>>>(x);
        k_reduce<<<KCOMP * 2, 256>>>();
        k_mstep<<<1, 256>>>();
    }
    k_write<<<(OUT_N + 255) / 256, 256>>>(out);
}

// round 13
// speedup vs baseline: 1.2921x; 1.0133x over previous
#include <cuda_runtime.h>

#define LDIM 26
#define KCOMP 64
#define BN 262144
#define NITER 8
#define WFLOOR 1e-5f
#define VFLOOR 1e-6f
#define LOG_PI_C 47.784803726642978f   // 26 * log(2*pi)
#define SHIFT 40.0f                    // fixed logit shift (replaces per-row max)

#define NBLK_F 296            // fused blocks (256 thr), 2 per SM, one wave
#define TILE 32
#define NTILE (BN / TILE)     // 8192
#define NSLOT NBLK_F          // 296 partial slots (one per block)
#define RHALF (NSLOT / 2)     // 148 slots per reduce-half
#define OUT_N (KCOMP + KCOMP*LDIM + KCOMP*LDIM*LDIM + 1)   // 44993

// ---------------- device state (no allocation allowed) ----------------
__device__ float g_w[KCOMP];
__device__ float g_mu[KCOMP * LDIM];
__device__ float g_sig[KCOMP * LDIM];
__device__ float g_Phn[KCOMP * LDIM];    // -0.5 / sigma
__device__ float g_MP[KCOMP * LDIM];     // mu / sigma
__device__ float g_C[KCOMP];             // log w - 0.5*(LOG_PI + logdet + quad) + SHIFT
__device__ float g_part[(size_t)NSLOT * KCOMP * 54];  // 4.1MB partials
__device__ float g_stat2[2][KCOMP * 54];
__device__ float g_llp[NBLK_F];
__device__ float g_ll;

// ---------------- init: normalize w0, copy mu0 / sigma0 ----------------
__global__ void k_init(const float* __restrict__ w0,
                       const float* __restrict__ mu0,
                       const float* __restrict__ s0) {
    __shared__ float s_sum;
    if (threadIdx.x == 0) {
        float s = 0.f;
        for (int k = 0; k < KCOMP; k++) s += w0[k];
        s_sum = s;
    }
    __syncthreads();
    for (int i = threadIdx.x; i < KCOMP * LDIM; i += blockDim.x) {
        g_mu[i]  = mu0[i];
        g_sig[i] = s0[i];
    }
    if (threadIdx.x < KCOMP) g_w[threadIdx.x] = w0[threadIdx.x] / s_sum;
}

// ---------------- prep (initial only) ----------------
__global__ void k_prep() {
    int k = blockIdx.x;
    int lane = threadIdx.x;
    float ld = 0.f, qd = 0.f;
    if (lane < LDIM) {
        float sg = g_sig[k * LDIM + lane];
        float mu = g_mu[k * LDIM + lane];
        float pr = 1.0f / sg;
        g_Phn[k * LDIM + lane] = -0.5f * pr;
        g_MP[k * LDIM + lane] = mu * pr;
        ld = logf(sg);
        qd = mu * mu * pr;
    }
    #pragma unroll
    for (int o = 16; o; o >>= 1) {
        ld += __shfl_xor_sync(0xffffffffu, ld, o);
        qd += __shfl_xor_sync(0xffffffffu, qd, o);
    }
    if (lane == 0)
        g_C[k] = logf(g_w[k]) - 0.5f * (LOG_PI_C + ld + qd) + SHIFT;
}

// ---------------- FUSED E-step + M-step stats ------------------------------
// Per 32-row tile:
//  stage:   x -> xs, x^2 -> x2s
//  phase1:  warp=(rq 0..3, khalf); lane owns comp k=(khalf<<5)+lane;
//           e = exp(C + sum_l x(MP + x Ph)) -> swizzled es[32][64]
//  phase2:  8 threads/row sum e -> rs = 1/s (smem), ll
//  phase3:  warp=(h, rgrp); thread owns k0=lane, k1=lane+32; p = e*rs;
//           accumulate z/px (h=0) and pxx (h=1) in registers.
// Posterior never touches gmem.
__global__ void __launch_bounds__(256, 2) k_fused(const float* __restrict__ x) {
    __shared__ __align__(16) float xs[TILE][28];
    __shared__ __align__(16) float x2s[TILE][28];
    __shared__ __align__(16) float es[TILE * KCOMP];
    __shared__ float rs_s[TILE];
    __shared__ float lls[TILE];
    __shared__ float comb[2][2][KCOMP][27];   // [slot][h][k][z|26 vals]

    int tid = threadIdx.x;
    int lane = tid & 31;
    int warp = tid >> 5;
    // phase1 mapping
    int khalf1 = warp & 1;
    int rq = warp >> 1;                  // 0..3, rows rq*8..rq*8+7
    int kp = (khalf1 << 5) + lane;       // owned comp in phase1
    int kq = kp >> 2, k3 = kp & 3;
    // phase2 mapping
    int r2 = tid >> 3, j8 = tid & 7;
    // phase3 mapping
    int h = warp & 1;
    int rgrp = warp >> 1;                // 0..3, rows rgrp*8..rgrp*8+7
    int k0 = lane, k1 = lane + 32;
    int sq0 = lane >> 2, e30 = lane & 3; // k0 quad/elem

    float MP[LDIM], Ph[LDIM];
    #pragma unroll
    for (int l = 0; l < LDIM; l++) {
        MP[l] = g_MP[kp * LDIM + l];
        Ph[l] = g_Phn[kp * LDIM + l];
    }
    float C = g_C[kp];

    float llacc = 0.f;
    float z0 = 0.f, z1 = 0.f;
    float a0[26], a1[26];
    #pragma unroll
    for (int j = 0; j < 26; j++) { a0[j] = 0.f; a1[j] = 0.f; }

    for (int t = blockIdx.x; t < NTILE; t += NBLK_F) {
        int rowbase = t * TILE;
        __syncthreads();                 // protect es/xs from previous tile
        // ---- stage 32 rows x 26 floats = 208 float4 ----
        if (tid < 208) {
            float4 v = ((const float4*)(x + (size_t)rowbase * LDIM))[tid];
            int e = tid * 4;
            float vv[4] = {v.x, v.y, v.z, v.w};
            #pragma unroll
            for (int j = 0; j < 4; j++) {
                int idx = e + j;
                int r = idx / LDIM, c = idx % LDIM;
                xs[r][c] = vv[j];
                x2s[r][c] = vv[j] * vv[j];
            }
        }
        __syncthreads();
        // ---- phase 1: logits + exp ----
        #pragma unroll
        for (int it = 0; it < 4; it++) {
            int ra = (rq << 3) + it * 2;
            int rb = ra + 1;
            const float4* A = (const float4*)xs[ra];
            const float4* B = (const float4*)xs[rb];
            float na = C, nb = C;
            #pragma unroll
            for (int i = 0; i < 6; i++) {
                float4 a = A[i];
                float4 b = B[i];
                #pragma unroll
                for (int j = 0; j < 4; j++) {
                    int l = 4 * i + j;
                    float av = j == 0 ? a.x : j == 1 ? a.y : j == 2 ? a.z : a.w;
                    float bv = j == 0 ? b.x : j == 1 ? b.y : j == 2 ? b.z : b.w;
                    float t0 = fmaf(av, Ph[l], MP[l]); na = fmaf(av, t0, na);
                    float t1 = fmaf(bv, Ph[l], MP[l]); nb = fmaf(bv, t1, nb);
                }
            }
            float2 a2 = *(const float2*)(&xs[ra][24]);
            float2 b2 = *(const float2*)(&xs[rb][24]);
            float u0 = fmaf(a2.x, Ph[24], MP[24]); na = fmaf(a2.x, u0, na);
            float u1 = fmaf(a2.y, Ph[25], MP[25]); na = fmaf(a2.y, u1, na);
            float u2 = fmaf(b2.x, Ph[24], MP[24]); nb = fmaf(b2.x, u2, nb);
            float u3 = fmaf(b2.y, Ph[25], MP[25]); nb = fmaf(b2.y, u3, nb);
            es[(ra << 6) + ((kq ^ (ra & 7)) << 2) + k3] = __expf(na);
            es[(rb << 6) + ((kq ^ (rb & 7)) << 2) + k3] = __expf(nb);
        }
        __syncthreads();
        // ---- phase 2: row sums -> rs, ll (order-agnostic over swizzle) ----
        {
            const float4* e4 = (const float4*)es;
            int qb = (r2 << 4) + (j8 << 1);
            float4 u = e4[qb];
            float4 v = e4[qb + 1];
            float s = ((u.x + u.y) + (u.z + u.w)) + ((v.x + v.y) + (v.z + v.w));
            s += __shfl_xor_sync(0xffffffffu, s, 1);
            s += __shfl_xor_sync(0xffffffffu, s, 2);
            s += __shfl_xor_sync(0xffffffffu, s, 4);
            if (j8 == 0) {
                rs_s[r2] = __frcp_rn(s);
                llacc += __logf(s) - SHIFT;
            }
        }
        __syncthreads();
        // ---- phase 3: stats accumulation ----
        #pragma unroll
        for (int rr = 0; rr < 8; rr++) {
            int r = (rgrp << 3) + rr;
            float rsv = rs_s[r];
            int sw = ((sq0 ^ (r & 7)) << 2) + e30;
            float e0 = es[(r << 6) + sw];
            float e1 = es[(r << 6) + 32 + sw];
            float p0 = e0 * rsv;
            float p1 = e1 * rsv;
            if (h == 0) { z0 += p0; z1 += p1; }
            const float4* V = (const float4*)(h ? x2s[r] : xs[r]);
            #pragma unroll
            for (int i = 0; i < 6; i++) {
                float4 v = V[i];
                a0[4*i]   = fmaf(p0, v.x, a0[4*i]);
                a1[4*i]   = fmaf(p1, v.x, a1[4*i]);
                a0[4*i+1] = fmaf(p0, v.y, a0[4*i+1]);
                a1[4*i+1] = fmaf(p1, v.y, a1[4*i+1]);
                a0[4*i+2] = fmaf(p0, v.z, a0[4*i+2]);
                a1[4*i+2] = fmaf(p1, v.z, a1[4*i+2]);
                a0[4*i+3] = fmaf(p0, v.w, a0[4*i+3]);
                a1[4*i+3] = fmaf(p1, v.w, a1[4*i+3]);
            }
            float4 v6 = V[6];
            a0[24] = fmaf(p0, v6.x, a0[24]);
            a1[24] = fmaf(p1, v6.x, a1[24]);
            a0[25] = fmaf(p0, v6.y, a0[25]);
            a1[25] = fmaf(p1, v6.y, a1[25]);
        }
    }

    // ---- ll gather ----
    __syncthreads();
    if (j8 == 0) lls[r2] = llacc;
    __syncthreads();
    if (tid == 0) {
        float s = 0.f;
        for (int i = 0; i < TILE; i++) s += lls[i];
        g_llp[blockIdx.x] = s;
    }

    // ---- combine rgrps 0..3 -> rgrp 0, one partial slot per block ----
    if (rgrp >= 2) {
        int slot = rgrp - 2;
        comb[slot][h][k0][0] = z0;
        comb[slot][h][k1][0] = z1;
        #pragma unroll
        for (int j = 0; j < 26; j++) {
            comb[slot][h][k0][1 + j] = a0[j];
            comb[slot][h][k1][1 + j] = a1[j];
        }
    }
    __syncthreads();
    if (rgrp < 2) {
        z0 += comb[rgrp][h][k0][0];
        z1 += comb[rgrp][h][k1][0];
        #pragma unroll
        for (int j = 0; j < 26; j++) {
            a0[j] += comb[rgrp][h][k0][1 + j];
            a1[j] += comb[rgrp][h][k1][1 + j];
        }
    }
    __syncthreads();
    if (rgrp == 1) {
        comb[0][h][k0][0] = z0;
        comb[0][h][k1][0] = z1;
        #pragma unroll
        for (int j = 0; j < 26; j++) {
            comb[0][h][k0][1 + j] = a0[j];
            comb[0][h][k1][1 + j] = a1[j];
        }
    }
    __syncthreads();
    if (rgrp == 0) {
        z0 += comb[0][h][k0][0];
        z1 += comb[0][h][k1][0];
        #pragma unroll
        for (int j = 0; j < 26; j++) {
            a0[j] += comb[0][h][k0][1 + j];
            a1[j] += comb[0][h][k1][1 + j];
        }
        float* d0 = g_part + ((size_t)blockIdx.x * KCOMP + k0) * 54;
        float* d1 = g_part + ((size_t)blockIdx.x * KCOMP + k1) * 54;
        if (h == 0) {
            d0[0] = z0;
            d1[0] = z1;
            #pragma unroll
            for (int j = 0; j < 26; j++) { d0[1 + j] = a0[j]; d1[1 + j] = a1[j]; }
        } else {
            #pragma unroll
            for (int j = 0; j < 26; j++) { d0[27 + j] = a0[j]; d1[27 + j] = a1[j]; }
        }
    }
}

// ---------------- reduce partials: one block per (k, slot-half) ----------------
__global__ void __launch_bounds__(256) k_reduce() {
    __shared__ float red[4][54];
    int bk = blockIdx.x >> 1;
    int half = blockIdx.x & 1;
    int tid = threadIdx.x;
    int j = tid & 63;
    int s = tid >> 6;
    if (j < 54) {
        float acc = 0.f;
        int base = half * RHALF;
        for (int slot = s; slot < RHALF; slot += 4)
            acc += g_part[((size_t)(base + slot) * KCOMP + bk) * 54 + j];
        red[s][j] = acc;
    }
    __syncthreads();
    if (tid < 54)
        g_stat2[half][bk * 54 + tid] = red[0][tid] + red[1][tid] + red[2][tid] + red[3][tid];
}

// ---------------- M-step finalize + fused prep ----------------
__global__ void __launch_bounds__(256) k_mstep() {
    __shared__ float s_w[KCOMP];
    __shared__ float s_ab[2];
    __shared__ float s_llp[64];
    int tid = threadIdx.x;

    if (tid < KCOMP) {
        float zk = g_stat2[0][tid * 54] + g_stat2[1][tid * 54];
        s_w[tid] = fmaxf(zk * (1.0f / BN), WFLOOR);
        float l = 0.f;
        for (int i = tid; i < NBLK_F; i += 64) l += g_llp[i];
        s_llp[tid] = l;
    }
    __syncthreads();
    if (tid == 0) {
        float sum = 0.f, ll = 0.f;
        for (int k = 0; k < KCOMP; k++) { sum += s_w[k]; ll += s_llp[k]; }
        float sf = WFLOOR * KCOMP;
        float a = (1.0f - sf) / (sum - sf);
        s_ab[0] = a;
        s_ab[1] = WFLOOR * (1.0f - a);
        g_ll = ll;
    }
    __syncthreads();
    if (tid < KCOMP) g_w[tid] = s_ab[0] * s_w[tid] + s_ab[1];

    for (int idx = tid; idx < KCOMP * LDIM; idx += 256) {
        int k = idx / LDIM, l = idx % LDIM;
        float z = g_stat2[0][k * 54] + g_stat2[1][k * 54];
        float zi = 1.0f / z;
        float px = g_stat2[0][k * 54 + 1 + l] + g_stat2[1][k * 54 + 1 + l];
        float pxx = g_stat2[0][k * 54 + 27 + l] + g_stat2[1][k * 54 + 27 + l];
        float mu = px * zi;
        float sg = fmaxf(pxx * zi - mu * mu, VFLOOR);
        g_mu[idx] = mu;
        g_sig[idx] = sg;
    }
    __syncthreads();

    int warp = tid >> 5, lane = tid & 31;
    for (int k = warp; k < KCOMP; k += 8) {
        float ld = 0.f, qd = 0.f;
        if (lane < LDIM) {
            float sg = g_sig[k * LDIM + lane];
            float mu = g_mu[k * LDIM + lane];
            float pr = 1.0f / sg;
            g_Phn[k * LDIM + lane] = -0.5f * pr;
            g_MP[k * LDIM + lane] = mu * pr;
            ld = logf(sg);
            qd = mu * mu * pr;
        }
        #pragma unroll
        for (int o = 16; o; o >>= 1) {
            ld += __shfl_xor_sync(0xffffffffu, ld, o);
            qd += __shfl_xor_sync(0xffffffffu, qd, o);
        }
        if (lane == 0)
            g_C[k] = logf(g_w[k]) - 0.5f * (LOG_PI_C + ld + qd) + SHIFT;
    }
}

// ---------------- output: w | mu | diag-expanded sigma | ll ----------------
__global__ void k_write(float* __restrict__ out) {
    int i = blockIdx.x * 256 + threadIdx.x;
    if (i >= OUT_N) return;
    float v;
    if (i < KCOMP) {
        v = g_w[i];
    } else if (i < KCOMP + KCOMP * LDIM) {
        v = g_mu[i - KCOMP];
    } else if (i < KCOMP + KCOMP * LDIM + KCOMP * LDIM * LDIM) {
        int j = i - (KCOMP + KCOMP * LDIM);
        int k = j / (LDIM * LDIM);
        int rc = j % (LDIM * LDIM);
        int r = rc / LDIM, c = rc % LDIM;
        v = (r == c) ? g_sig[k * LDIM + r] : 0.f;
    } else {
        v = g_ll;
    }
    out[i] = v;
}

extern "C" void kernel_launch(void* const* d_in, const int* in_sizes, int n_in,
                              void* d_out, int out_size) {
    const float* x   = (const float*)d_in[0];
    const float* w0  = (const float*)d_in[1];
    const float* mu0 = (const float*)d_in[2];
    const float* s0  = (const float*)d_in[3];
    float* out = (float*)d_out;

    k_init<<<1, 256>>>(w0, mu0, s0);
    k_prep<<<KCOMP, 32>>>();
    for (int it = 0; it < NITER; it++) {
        k_fused<<<NBLK_F, 256>>>(x);
        k_reduce<<<KCOMP * 2, 256>>>();
        k_mstep<<<1, 256>>>();
    }
    k_write<<<(OUT_N + 255) / 256, 256>>>(out);
}